// round 14
// baseline (speedup 1.0000x reference)
#include <cuda_runtime.h>
#include <cstdint>

#define FDIM   1024
#define FV     256            // float4 per row
#define DDOM   8
#define MAXN   16384
#define NSEG   148            // 1 CTA per SM, zero wave imbalance
#define MAXR   128            // max rows per segment (111 used)
#define NBUF   4              // smem ring buffers
#define BATCH  5              // rows per buffer (4 KB each)
#define RA     8              // rows per apply block
#define EPSV   1e-5f

#define STATS_SMEM (NBUF * BATCH * 4096 + NBUF * 8)

// ---------------- scratch ----------------
__device__ float g_P[NSEG * DDOM * FDIM];     // partial sum(x)
__device__ float g_Q[NSEG * DDOM * FDIM];     // partial sum(x*x)
__device__ int   g_c[NSEG * DDOM];            // per-seg domain counts
__device__ unsigned char g_ydom[MAXN];        // decoded domain per row
__device__ float g_A[DDOM * FDIM];            // gamma * inv
__device__ float g_B[DDOM * FDIM];            // beta - mean * gamma * inv

// int64-vs-int32 y detection (odd 32-bit words all zero over 32 values)
__device__ __forceinline__ int detect64(const int* __restrict__ y) {
    const int4* p = (const int4*)y;
    int acc = 0;
#pragma unroll
    for (int i = 0; i < 8; i++) { int4 a = p[i]; acc |= a.y | a.w; }
    return acc == 0;
}

#define ACCUM(v)                                        \
    s1.x += v.x; s1.y += v.y; s1.z += v.z; s1.w += v.w; \
    s2.x = fmaf(v.x, v.x, s2.x);                        \
    s2.y = fmaf(v.y, v.y, s2.y);                        \
    s2.z = fmaf(v.z, v.z, s2.z);                        \
    s2.w = fmaf(v.w, v.w, s2.w);

#define MWAIT(mboff, phase) do {                                              \
    asm volatile("{\n\t.reg .pred P1;\n\t"                                    \
        "WL_%=:\n\t"                                                          \
        "mbarrier.try_wait.parity.acquire.cta.shared::cta.b64 P1, [%0], %1, 0x989680;\n\t" \
        "@P1 bra.uni WD_%=;\n\t"                                              \
        "bra.uni WL_%=;\n\t"                                                  \
        "WD_%=:\n\t}"                                                         \
        :: "r"(mboff), "r"(phase) : "memory");                                \
} while (0)

// ---- K1: stats. 148 blocks x 111 rows; TMA bulk ring; domain-sorted. ----
__global__ __launch_bounds__(256, 1)
void stats_k(const float4* __restrict__ x4, const int* __restrict__ yi,
             int n, int rlo, int rem) {
    extern __shared__ char dynsm[];     // [NBUF*BATCH*4096 data][NBUF*8 mbar]
    __shared__ int flat[MAXR];          // row*FV, domain-sorted
    __shared__ int cnt[DDOM];
    __shared__ int fill[DDOM];

    const int tid  = threadIdx.x;
    const int b    = blockIdx.x;
    const int base = b * rlo + min(b, rem);
    const int nr   = min(rlo + (b < rem ? 1 : 0), n - base);
    const int rend = base + nr;

    uint32_t sbase;
    asm("{ .reg .u64 t; cvta.to.shared.u64 t, %1; cvt.u32.u64 %0, t; }"
        : "=r"(sbase) : "l"(dynsm));
    const uint32_t smb = sbase + NBUF * BATCH * 4096;

    if (tid < DDOM) cnt[tid] = 0;
    if (tid == 0) {
#pragma unroll
        for (int q = 0; q < NBUF; q++)
            asm volatile("mbarrier.init.shared.b64 [%0], %1;"
                         :: "r"(smb + q * 8), "r"(1) : "memory");
    }
    __syncthreads();

    if (tid < 32) {   // warp 0: TWO-PASS deterministic counting sort
        const int is64 = detect64(yi);
        const int ntile = (nr + 31) >> 5;          // <= 4
        int dloc[4] = {-1, -1, -1, -1};

        // Pass A: count per domain across tiles; cache lane domains.
        for (int t = 0; t < ntile; t++) {
            const int r = base + t * 32 + tid;
            const int d = (r < rend) ? (is64 ? yi[2 * r] : yi[r]) : -1;
            dloc[t] = d;
            const unsigned m = __match_any_sync(0xffffffffu, d);
            if (d >= 0) {
                g_ydom[r] = (unsigned char)d;
                if ((int)(__ffs(m) - 1) == tid) cnt[d] += __popc(m);
            }
            __syncwarp();
        }
        // Prefix offsets.
        if (tid == 0) {
            int run = 0;
#pragma unroll
            for (int d = 0; d < DDOM; d++) { fill[d] = run; run += cnt[d]; }
        }
        __syncwarp();
        // Pass B: place rows at fill[d] + rank; leaders advance cursors.
        for (int t = 0; t < ntile; t++) {
            const int d = dloc[t];
            const unsigned m = __match_any_sync(0xffffffffu, d);
            const int rank = __popc(m & ((1u << tid) - 1u));
            const int off = (d >= 0) ? fill[d] : 0;
            __syncwarp();
            if (d >= 0) {
                flat[off + rank] = (base + t * 32 + tid) * FV;
                if ((int)(__ffs(m) - 1) == tid) fill[d] = off + __popc(m);
            }
            __syncwarp();
        }
    }
    __syncthreads();

    const char* xb = (const char*)x4;
    const int nb = (nr + BATCH - 1) / BATCH;

#define BISSUE(bx) do {                                                       \
        if (tid == 0) {                                                       \
            const int _st  = (bx) * BATCH;                                    \
            const int _cnt = min(BATCH, nr - _st);                            \
            const uint32_t _mb = smb + ((bx) % NBUF) * 8;                     \
            asm volatile("mbarrier.arrive.expect_tx.shared.b64 _, [%0], %1;"  \
                         :: "r"(_mb), "r"(_cnt * 4096) : "memory");           \
            for (int _r = 0; _r < _cnt; _r++) {                               \
                const uint32_t _dst = sbase + (((bx) % NBUF) * BATCH + _r) * 4096; \
                const char* _src = xb + ((size_t)flat[_st + _r] << 4);        \
                asm volatile(                                                 \
                    "cp.async.bulk.shared::cta.global.mbarrier::complete_tx::bytes " \
                    "[%0], [%1], %2, [%3];"                                   \
                    :: "r"(_dst), "l"(_src), "r"(4096), "r"(_mb) : "memory"); \
            }                                                                 \
        }                                                                     \
    } while (0)

    {
        const int npro = min(NBUF, nb);
        for (int q = 0; q < npro; q++) BISSUE(q);
    }

    const float4* bufp = (const float4*)dynsm;
    int ph0 = 0, ph1 = 0, ph2 = 0, ph3 = 0;
    int i = 0, inb = 0, bidx = 0;

#pragma unroll
    for (int d = 0; d < DDOM; d++) {
        const int nd = cnt[d];
        float4 s1 = make_float4(0.f, 0.f, 0.f, 0.f);
        float4 s2 = make_float4(0.f, 0.f, 0.f, 0.f);
        for (int k = 0; k < nd; k++) {
            if (inb == 0) {                       // entering a new batch: wait
                const int q = bidx & (NBUF - 1);
                const uint32_t mboff = smb + q * 8;
                switch (q) {
                    case 0: MWAIT(mboff, ph0); ph0 ^= 1; break;
                    case 1: MWAIT(mboff, ph1); ph1 ^= 1; break;
                    case 2: MWAIT(mboff, ph2); ph2 ^= 1; break;
                    default: MWAIT(mboff, ph3); ph3 ^= 1; break;
                }
            }
            float4 v = bufp[((bidx & (NBUF - 1)) * BATCH + inb) * 256 + tid];
            ACCUM(v);
            i++; inb++;
            if (inb == BATCH || i == nr) {        // batch consumed: recycle slot
                __syncthreads();
                const int nxt = bidx + NBUF;
                if (nxt < nb) BISSUE(nxt);
                inb = 0; bidx++;
            }
        }
        const size_t o = ((size_t)b * DDOM + d) * FV + tid;
        ((float4*)g_P)[o] = s1;
        ((float4*)g_Q)[o] = s2;
    }
    if (tid < DDOM) g_c[b * DDOM + tid] = cnt[tid];
#undef BISSUE
}

// ---- K2: fold segments -> A/B. 128 blocks = 8 dom x 16 f4-slices. ----
__global__ __launch_bounds__(256)
void finalize_k(const float* __restrict__ gamma, const float* __restrict__ beta,
                int nseg) {
    __shared__ float4 smP[16][16];
    __shared__ float4 smQ[16][16];
    __shared__ int    scnt[256];
    const int tid  = threadIdx.x;
    const int d    = blockIdx.x >> 4;
    const int fs   = blockIdx.x & 15;
    const int w    = tid >> 5, lane = tid & 31;
    const int c    = lane & 15;            // f4 within slice
    const int sp   = lane >> 4;            // segment parity within pair
    const int f4   = fs * 16 + c;

    {
        int cc = 0;
        for (int s = tid; s < nseg; s += 256) cc += g_c[s * DDOM + d];
        scnt[tid] = cc;
    }

    const float4* P4 = (const float4*)g_P;
    const float4* Q4 = (const float4*)g_Q;
    float4 ap = make_float4(0.f, 0.f, 0.f, 0.f);
    float4 aq = make_float4(0.f, 0.f, 0.f, 0.f);
    for (int s0 = w * 2; s0 < nseg; s0 += 16) {
        const int s = s0 + sp;
        if (s < nseg) {
            const size_t o = ((size_t)s * DDOM + d) * FV + f4;
            float4 p = P4[o], q = Q4[o];
            ap.x += p.x; ap.y += p.y; ap.z += p.z; ap.w += p.w;
            aq.x += q.x; aq.y += q.y; aq.z += q.z; aq.w += q.w;
        }
    }
    smP[w * 2 + sp][c] = ap;
    smQ[w * 2 + sp][c] = aq;
    __syncthreads();

    for (int off = 128; off > 0; off >>= 1) {
        if (tid < off) scnt[tid] += scnt[tid + off];
        __syncthreads();
    }
    const float cct = (float)scnt[0];

    if (tid < 16) {                        // one lane per f4 position
        float4 s1 = smP[0][tid], s2 = smQ[0][tid];
#pragma unroll
        for (int rrow = 1; rrow < 16; rrow++) {
            float4 p = smP[rrow][tid], q = smQ[rrow][tid];
            s1.x += p.x; s1.y += p.y; s1.z += p.z; s1.w += p.w;
            s2.x += q.x; s2.y += q.y; s2.z += q.z; s2.w += q.w;
        }
        const int o = d * FDIM + (fs * 16 + tid) * 4;
        float4 A, Bv;
        if (cct > 1.5f) {
            const float rc = 1.0f / cct;
            float4 g  = *(const float4*)(gamma + o);
            float4 be = *(const float4*)(beta + o);
            float mx = s1.x * rc, my = s1.y * rc, mz = s1.z * rc, mw = s1.w * rc;
            float vx = fmaf(-mx, mx, s2.x * rc);
            float vy = fmaf(-my, my, s2.y * rc);
            float vz = fmaf(-mz, mz, s2.z * rc);
            float vw = fmaf(-mw, mw, s2.w * rc);
            A.x = g.x * rsqrtf(vx + EPSV);
            A.y = g.y * rsqrtf(vy + EPSV);
            A.z = g.z * rsqrtf(vz + EPSV);
            A.w = g.w * rsqrtf(vw + EPSV);
            Bv.x = fmaf(-mx, A.x, be.x);
            Bv.y = fmaf(-my, A.y, be.y);
            Bv.z = fmaf(-mz, A.z, be.z);
            Bv.w = fmaf(-mw, A.w, be.w);
        } else if (cct > 0.5f) {   // single-sample domain: out = x
            A  = make_float4(1.f, 1.f, 1.f, 1.f);
            Bv = make_float4(0.f, 0.f, 0.f, 0.f);
        } else {                   // empty domain (unused)
            A  = make_float4(0.f, 0.f, 0.f, 0.f);
            Bv = make_float4(0.f, 0.f, 0.f, 0.f);
        }
        *(float4*)(g_A + o) = A;
        *(float4*)(g_B + o) = Bv;
    }
}

// ---- K3: out = A[d]*x + B[d]; 8 v-loads issued before consumption ----
__global__ __launch_bounds__(256)
void apply_k(const float4* __restrict__ x4, float4* __restrict__ o4, int n) {
    __shared__ int sd[RA];
    const int tid = threadIdx.x;
    const int r0  = blockIdx.x * RA;

    if (tid < RA) {
        const int r = r0 + tid;
        sd[tid] = (r < n) ? (int)g_ydom[r] : 0;
    }
    __syncthreads();

    const float4* A4 = (const float4*)g_A;
    const float4* B4 = (const float4*)g_B;

    if (r0 + RA <= n) {
        const float4* p = x4 + (size_t)r0 * FV + tid;
        float4 v[RA];
#pragma unroll
        for (int j = 0; j < RA; j++) v[j] = __ldcs(p + j * FV);   // MLP 8
#pragma unroll
        for (int j = 0; j < RA; j++) {
            const int dd = sd[j];
            const float4 a = __ldg(A4 + dd * FV + tid);
            const float4 b = __ldg(B4 + dd * FV + tid);
            float4 w;
            w.x = fmaf(v[j].x, a.x, b.x);
            w.y = fmaf(v[j].y, a.y, b.y);
            w.z = fmaf(v[j].z, a.z, b.z);
            w.w = fmaf(v[j].w, a.w, b.w);
            __stcs(o4 + (size_t)(r0 + j) * FV + tid, w);
        }
    } else {
        for (int j = 0; j < RA; j++) {
            const int rr = r0 + j;
            if (rr >= n) break;
            const int dd = sd[j];
            float4 v = __ldcs(x4 + (size_t)rr * FV + tid);
            float4 a = __ldg(A4 + dd * FV + tid);
            float4 b = __ldg(B4 + dd * FV + tid);
            float4 w;
            w.x = fmaf(v.x, a.x, b.x); w.y = fmaf(v.y, a.y, b.y);
            w.z = fmaf(v.z, a.z, b.z); w.w = fmaf(v.w, a.w, b.w);
            __stcs(o4 + (size_t)rr * FV + tid, w);
        }
    }
}

extern "C" void kernel_launch(void* const* d_in, const int* in_sizes, int n_in,
                              void* d_out, int out_size) {
    const float* x     = (const float*)d_in[0];
    const int*   y     = (const int*)d_in[1];
    const float* gamma = (const float*)d_in[2];
    const float* beta  = (const float*)d_in[3];
    float* out = (float*)d_out;

    const int n   = in_sizes[1];
    const int rlo = n / NSEG;                  // 110
    const int rem = n - rlo * NSEG;            // 104

    cudaFuncSetAttribute(stats_k, cudaFuncAttributeMaxDynamicSharedMemorySize,
                         STATS_SMEM);
    stats_k<<<NSEG, 256, STATS_SMEM>>>((const float4*)x, y, n, rlo, rem);
    finalize_k<<<DDOM * 16, 256>>>(gamma, beta, NSEG);
    apply_k<<<(n + RA - 1) / RA, 256>>>((const float4*)x, (float4*)out, n);
}

// round 15
// speedup vs baseline: 1.0592x; 1.0592x over previous
#include <cuda_runtime.h>
#include <cstdint>

#define FDIM   1024
#define FV     256            // float4 per row
#define DDOM   8
#define MAXN   16384
#define NSEG   296            // 2 full waves on 148 SMs
#define MAXR   64             // max rows per segment (56)
#define DEPTH  10             // stats cp.async depth (rows in flight)
#define RA     8              // rows per apply block
#define EPSV   1e-5f

// ---------------- scratch ----------------
__device__ float g_P[NSEG * DDOM * FDIM];     // partial sum(x)
__device__ float g_Q[NSEG * DDOM * FDIM];     // partial sum(x*x)
__device__ int   g_c[NSEG * DDOM];            // per-seg domain counts
__device__ unsigned char g_ydom[MAXN];        // decoded domain per row
__device__ float g_A[DDOM * FDIM];            // gamma * inv
__device__ float g_B[DDOM * FDIM];            // beta - mean * gamma * inv

// int64-vs-int32 y detection (odd 32-bit words all zero over 32 values)
__device__ __forceinline__ int detect64(const int* __restrict__ y) {
    const int4* p = (const int4*)y;
    int acc = 0;
#pragma unroll
    for (int i = 0; i < 8; i++) { int4 a = p[i]; acc |= a.y | a.w; }
    return acc == 0;
}

#define ACCUM(v)                                        \
    s1.x += v.x; s1.y += v.y; s1.z += v.z; s1.w += v.w; \
    s2.x = fmaf(v.x, v.x, s2.x);                        \
    s2.y = fmaf(v.y, v.y, s2.y);                        \
    s2.z = fmaf(v.z, v.z, s2.z);                        \
    s2.w = fmaf(v.w, v.w, s2.w);

#define FADD4(acc, p) do {                                      \
    acc.x += (p).x; acc.y += (p).y; acc.z += (p).z; acc.w += (p).w; } while (0)

// ---- K1: stats via cp.async pipeline over domain-sorted flat list (R11) ----
__global__ __launch_bounds__(256, 2)
void stats_k(const float4* __restrict__ x4, const int* __restrict__ yi,
             int n, int rlo, int rem) {
    __shared__ float4 buf[DEPTH][256];   // 40 KB ring
    __shared__ int flat[MAXR];           // row*FV, domain-sorted
    __shared__ int cnt[DDOM];
    __shared__ int fill[DDOM];

    const int tid  = threadIdx.x;
    const int b    = blockIdx.x;
    const int base = b * rlo + min(b, rem);
    const int nr   = min(rlo + (b < rem ? 1 : 0), n - base);

    if (tid < DDOM) cnt[tid] = 0;
    __syncthreads();

    if (tid < 32) {   // warp 0: deterministic 2-tile counting sort -> flat[]
        const int is64 = detect64(yi);
        const int r0 = base + tid;
        const int r1 = base + 32 + tid;
        const int da = (tid < nr)      ? (is64 ? yi[2 * r0] : yi[r0]) : -1;
        const int db = (32 + tid < nr) ? (is64 ? yi[2 * r1] : yi[r1]) : -1;
        const unsigned ma = __match_any_sync(0xffffffffu, da);
        if (da >= 0) {
            g_ydom[r0] = (unsigned char)da;
            if ((int)(__ffs(ma) - 1) == tid) cnt[da] = __popc(ma);
        }
        __syncwarp();
        const unsigned mb = __match_any_sync(0xffffffffu, db);
        if (db >= 0) {
            g_ydom[r1] = (unsigned char)db;
            if ((int)(__ffs(mb) - 1) == tid) cnt[db] += __popc(mb);
        }
        __syncwarp();
        if (tid == 0) {
            int run = 0;
#pragma unroll
            for (int d = 0; d < DDOM; d++) { fill[d] = run; run += cnt[d]; }
        }
        __syncwarp();
        const int ra = __popc(ma & ((1u << tid) - 1u));
        if (da >= 0) flat[fill[da] + ra] = r0 * FV;
        __syncwarp();
        if (da >= 0 && (int)(__ffs(ma) - 1) == tid) fill[da] += __popc(ma);
        __syncwarp();
        const int rb = __popc(mb & ((1u << tid) - 1u));
        if (db >= 0) flat[fill[db] + rb] = r1 * FV;
    }
    __syncthreads();

    uint32_t sbuf;
    asm("{ .reg .u64 t; cvta.to.shared.u64 t, %1; cvt.u32.u64 %0, t; }"
        : "=r"(sbuf) : "l"(buf));
    const char* xb = (const char*)x4;
    const uint32_t myoff = tid * 16;

#define ISSUE(k) do {                                                        \
        uint32_t _da = sbuf + ((k) % DEPTH) * 4096 + myoff;                  \
        const void* _g = xb + ((size_t)(flat[(k)] + tid) << 4);              \
        asm volatile("cp.async.cg.shared.global [%0], [%1], 16;"             \
                     :: "r"(_da), "l"(_g) : "memory");                       \
        asm volatile("cp.async.commit_group;" ::: "memory");                 \
    } while (0)

    const int np = min(DEPTH, nr);
    for (int k = 0; k < np; k++) ISSUE(k);
    int issued = np;
    int i = 0;

#pragma unroll
    for (int d = 0; d < DDOM; d++) {
        const int nd = cnt[d];
        float4 s1 = make_float4(0.f, 0.f, 0.f, 0.f);
        float4 s2 = make_float4(0.f, 0.f, 0.f, 0.f);
        for (int k = 0; k < nd; k++, i++) {
            if (issued < nr) {
                asm volatile("cp.async.wait_group %0;" :: "n"(DEPTH - 1) : "memory");
            } else {
                asm volatile("cp.async.wait_group 0;" ::: "memory");
            }
            float4 v = buf[i % DEPTH][tid];
            if (issued < nr) { ISSUE(issued); issued++; }
            ACCUM(v);
        }
        const size_t o = ((size_t)b * DDOM + d) * FV + tid;
        ((float4*)g_P)[o] = s1;
        ((float4*)g_Q)[o] = s2;
    }
    if (tid < DDOM) g_c[b * DDOM + tid] = cnt[tid];
#undef ISSUE
}

// ---- K2: fold segments -> A/B. 64 blocks; unroll-4 seg-steps (MLP 8). ----
__global__ __launch_bounds__(256)
void finalize_k(const float* __restrict__ gamma, const float* __restrict__ beta,
                int nseg) {
    __shared__ float4 smP[8][32];
    __shared__ float4 smQ[8][32];
    __shared__ int    scnt[256];
    const int tid  = threadIdx.x;
    const int d    = blockIdx.x >> 3;
    const int fs   = blockIdx.x & 7;
    const int w    = tid >> 5, lane = tid & 31;
    const int posIdx = fs * 32 + lane;

    {
        int c = 0;
        for (int s = tid; s < nseg; s += 256) c += g_c[s * DDOM + d];
        scnt[tid] = c;
    }

    const float4* P4 = (const float4*)g_P;
    const float4* Q4 = (const float4*)g_Q;
    const size_t segstep = (size_t)DDOM * FV;      // f4 stride between segments
    const size_t ob = (size_t)d * FV + posIdx;

    float4 ap0 = make_float4(0.f, 0.f, 0.f, 0.f), ap1 = ap0, ap2 = ap0, ap3 = ap0;
    float4 aq0 = ap0, aq1 = ap0, aq2 = ap0, aq3 = ap0;
    int s = w;
    for (; s + 24 < nseg; s += 32) {               // 4 seg-steps: 8 loads in flight
        const size_t o0 = ob + (size_t)s * segstep;
        const size_t o1 = o0 + 8 * segstep;
        const size_t o2 = o0 + 16 * segstep;
        const size_t o3 = o0 + 24 * segstep;
        float4 p0 = P4[o0], p1 = P4[o1], p2 = P4[o2], p3 = P4[o3];
        float4 q0 = Q4[o0], q1 = Q4[o1], q2 = Q4[o2], q3 = Q4[o3];
        FADD4(ap0, p0); FADD4(ap1, p1); FADD4(ap2, p2); FADD4(ap3, p3);
        FADD4(aq0, q0); FADD4(aq1, q1); FADD4(aq2, q2); FADD4(aq3, q3);
    }
    for (; s < nseg; s += 8) {
        const size_t o = ob + (size_t)s * segstep;
        float4 p = P4[o], q = Q4[o];
        FADD4(ap0, p); FADD4(aq0, q);
    }
    FADD4(ap0, ap1); FADD4(ap2, ap3); FADD4(ap0, ap2);
    FADD4(aq0, aq1); FADD4(aq2, aq3); FADD4(aq0, aq2);
    smP[w][lane] = ap0;
    smQ[w][lane] = aq0;
    __syncthreads();

    for (int off = 128; off > 0; off >>= 1) {
        if (tid < off) scnt[tid] += scnt[tid + off];
        __syncthreads();
    }
    const float c = (float)scnt[0];

    if (w == 0) {
        float4 s1 = smP[0][lane], s2 = smQ[0][lane];
#pragma unroll
        for (int ww = 1; ww < 8; ww++) {
            FADD4(s1, smP[ww][lane]);
            FADD4(s2, smQ[ww][lane]);
        }
        const int o = d * FDIM + posIdx * 4;
        float4 A, Bv;
        if (c > 1.5f) {
            const float rc = 1.0f / c;
            float4 g  = *(const float4*)(gamma + o);
            float4 be = *(const float4*)(beta + o);
            float mx = s1.x * rc, my = s1.y * rc, mz = s1.z * rc, mw = s1.w * rc;
            float vx = fmaf(-mx, mx, s2.x * rc);
            float vy = fmaf(-my, my, s2.y * rc);
            float vz = fmaf(-mz, mz, s2.z * rc);
            float vw = fmaf(-mw, mw, s2.w * rc);
            A.x = g.x * rsqrtf(vx + EPSV);
            A.y = g.y * rsqrtf(vy + EPSV);
            A.z = g.z * rsqrtf(vz + EPSV);
            A.w = g.w * rsqrtf(vw + EPSV);
            Bv.x = fmaf(-mx, A.x, be.x);
            Bv.y = fmaf(-my, A.y, be.y);
            Bv.z = fmaf(-mz, A.z, be.z);
            Bv.w = fmaf(-mw, A.w, be.w);
        } else if (c > 0.5f) {   // single-sample domain: out = x
            A  = make_float4(1.f, 1.f, 1.f, 1.f);
            Bv = make_float4(0.f, 0.f, 0.f, 0.f);
        } else {                 // empty domain (unused)
            A  = make_float4(0.f, 0.f, 0.f, 0.f);
            Bv = make_float4(0.f, 0.f, 0.f, 0.f);
        }
        *(float4*)(g_A + o) = A;
        *(float4*)(g_B + o) = Bv;
    }
}

// ---- K3: out = A[d]*x + B[d]; 8 v-loads issued before consumption ----
__global__ __launch_bounds__(256)
void apply_k(const float4* __restrict__ x4, float4* __restrict__ o4, int n) {
    __shared__ int sd[RA];
    const int tid = threadIdx.x;
    const int r0  = blockIdx.x * RA;

    if (tid < RA) {
        const int r = r0 + tid;
        sd[tid] = (r < n) ? (int)g_ydom[r] : 0;
    }
    __syncthreads();

    const float4* A4 = (const float4*)g_A;
    const float4* B4 = (const float4*)g_B;

    if (r0 + RA <= n) {
        const float4* p = x4 + (size_t)r0 * FV + tid;
        float4 v[RA];
#pragma unroll
        for (int j = 0; j < RA; j++) v[j] = __ldcs(p + j * FV);   // MLP 8
#pragma unroll
        for (int j = 0; j < RA; j++) {
            const int dd = sd[j];
            const float4 a = __ldg(A4 + dd * FV + tid);
            const float4 b = __ldg(B4 + dd * FV + tid);
            float4 w;
            w.x = fmaf(v[j].x, a.x, b.x);
            w.y = fmaf(v[j].y, a.y, b.y);
            w.z = fmaf(v[j].z, a.z, b.z);
            w.w = fmaf(v[j].w, a.w, b.w);
            __stcs(o4 + (size_t)(r0 + j) * FV + tid, w);
        }
    } else {
        for (int j = 0; j < RA; j++) {
            const int rr = r0 + j;
            if (rr >= n) break;
            const int dd = sd[j];
            float4 v = __ldcs(x4 + (size_t)rr * FV + tid);
            float4 a = __ldg(A4 + dd * FV + tid);
            float4 b = __ldg(B4 + dd * FV + tid);
            float4 w;
            w.x = fmaf(v.x, a.x, b.x); w.y = fmaf(v.y, a.y, b.y);
            w.z = fmaf(v.z, a.z, b.z); w.w = fmaf(v.w, a.w, b.w);
            __stcs(o4 + (size_t)rr * FV + tid, w);
        }
    }
}

extern "C" void kernel_launch(void* const* d_in, const int* in_sizes, int n_in,
                              void* d_out, int out_size) {
    const float* x     = (const float*)d_in[0];
    const int*   y     = (const int*)d_in[1];
    const float* gamma = (const float*)d_in[2];
    const float* beta  = (const float*)d_in[3];
    float* out = (float*)d_out;

    const int n   = in_sizes[1];
    const int rlo = n / NSEG;
    const int rem = n - rlo * NSEG;

    stats_k<<<NSEG, 256>>>((const float4*)x, y, n, rlo, rem);
    finalize_k<<<DDOM * 8, 256>>>(gamma, beta, NSEG);
    apply_k<<<(n + RA - 1) / RA, 256>>>((const float4*)x, (float4*)out, n);
}